// round 11
// baseline (speedup 1.0000x reference)
#include <cuda_runtime.h>

// ---------------- problem constants ----------------
#define D_      128
#define TWO_D   256
#define NINIT   100000
#define LVLS    64
#define MM      4096
#define NRULES  256
#define NTOT    (NINIT + LVLS * MM)   // 362144

#define EVAL_BLOCKS 1024
#define CHUNK 8      // nodes per pipelined chunk
#define WIN   64     // node-index window staged per rule

// dynamic smem layout for k_level:
//   w_s    float2[256][32]            65536 B  (this half's weight columns)
//   pe     float [2][CHUNK][TWO_D]    16384 B  (raw gathered parents, dbl buf)
//   s_m    int[WIN]                     256 B
//   s_par  int[WIN][2]                  512 B
#define WS_BYTES  65536
#define PE_BYTES  (2 * CHUNK * TWO_D * 4)
#define SMEM_BYTES (WS_BYTES + PE_BYTES + WIN * 4 + WIN * 8 + 128)

// ---------------- device scratch (static: no allocs allowed) ----------------
__device__ float  g_store[(size_t)NTOT * D_];           // ~185 MB embedding store
__device__ int    g_order[LVLS * MM];                   // node ids grouped by rule, per level
__device__ int    g_off[LVLS * (NRULES + 1)];           // per-level rule offsets
__device__ double g_part[EVAL_BLOCKS * 8];              // eval partial sums

// ---------------- helpers ----------------
__device__ __forceinline__ void cpa16(unsigned dst, const void* src) {
    asm volatile("cp.async.cg.shared.global [%0], [%1], 16;" :: "r"(dst), "l"(src));
}
#define CPA_COMMIT() asm volatile("cp.async.commit_group;")
#define CPA_WAIT(n)  asm volatile("cp.async.wait_group %0;" :: "n"(n))

__device__ __forceinline__ float softplusf(float x) {
    return fmaxf(x, 0.0f) + log1pf(expf(-fabsf(x)));
}

// ---------------- 1. init embeddings ----------------
__global__ void k_init(const float* __restrict__ thax_table,
                       const float* __restrict__ sine_table,
                       const int* __restrict__ init_thax,
                       const int* __restrict__ init_sine) {
    int idx = blockIdx.x * blockDim.x + threadIdx.x;   // one float4 each
    if (idx >= NINIT * 32) return;
    int row = idx >> 5, q = idx & 31;
    int t = init_thax[row], s = init_sine[row];
    const float4 a = *(const float4*)(thax_table + (size_t)t * D_ + q * 4);
    const float4 b = *(const float4*)(sine_table + (size_t)s * D_ + q * 4);
    float4 o; o.x = a.x + b.x; o.y = a.y + b.y; o.z = a.z + b.z; o.w = a.w + b.w;
    *(float4*)(g_store + (size_t)row * D_ + q * 4) = o;
}

// ---------------- 2. bucket nodes by rule, per level ----------------
__global__ void k_group(const int* __restrict__ rules) {
    int l = blockIdx.x;
    int tid = threadIdx.x;                    // 256 threads
    __shared__ int cnt[NRULES];
    __shared__ int base[NRULES];
    cnt[tid] = 0;
    __syncthreads();
    for (int m = tid; m < MM; m += 256)
        atomicAdd(&cnt[rules[l * MM + m]], 1);
    __syncthreads();
    if (tid == 0) {
        int acc = 0;
        for (int r = 0; r < NRULES; r++) { base[r] = acc; acc += cnt[r]; }
    }
    __syncthreads();
    g_off[l * (NRULES + 1) + tid] = base[tid];
    if (tid == 0) g_off[l * (NRULES + 1) + NRULES] = MM;
    cnt[tid] = 0;
    __syncthreads();
    for (int m = tid; m < MM; m += 256) {
        int r = rules[l * MM + m];
        int pos = base[r] + atomicAdd(&cnt[r], 1);
        g_order[l * MM + pos] = m;            // order within a rule irrelevant
    }
}

// ---------------- 3. level kernel: per-rule MLP, fully cp.async-pipelined ----
// Block = 256 threads = 32 col-pairs (j) x 8 nodes (g), covers 64 of 128
// output cols (half = blockIdx.x & 1). Weights bulk-staged via one cp.async
// group; parent gathers cp.async'd per 8-node chunk, double-buffered one
// chunk ahead, so no warp stalls on global loads in steady state.
__global__ void __launch_bounds__(256) k_level(
    const float* __restrict__ rule_W, const float* __restrict__ rule_b,
    const int* __restrict__ parents, int lvl) {

    int r    = blockIdx.x >> 1;
    int half = blockIdx.x & 1;
    int off0 = g_off[lvl * (NRULES + 1) + r];
    int off1 = g_off[lvl * (NRULES + 1) + r + 1];
    int c = off1 - off0;
    if (c == 0) return;

    extern __shared__ char smem_raw[];
    float2* w_s = (float2*)smem_raw;                         // [256][32]
    float*  pe  = (float*)(smem_raw + WS_BYTES);             // [2][CHUNK][256]
    int* s_m    = (int*)(smem_raw + WS_BYTES + PE_BYTES);    // [WIN]
    int* s_par  = s_m + WIN;                                 // [WIN][2]

    int tid = threadIdx.x;
    int j   = tid & 31;            // col-pair
    int g   = tid >> 5;            // node slot 0..7
    int cb  = half * 64 + 2 * j;   // output column base

    // ---- bulk-stage this block's 64KB weight half (async, group 0) ----
    {
        const char* wsrc = (const char*)(rule_W + (size_t)r * TWO_D * D_ + half * 64);
        unsigned wdst = (unsigned)__cvta_generic_to_shared(w_s);
#pragma unroll
        for (int i = 0; i < 16; i++) {
            int s  = i * 256 + tid;          // 0..4095 16B segments
            int k  = s >> 4, sg = s & 15;
            cpa16(wdst + (unsigned)(k * 256 + sg * 16),
                  wsrc + (size_t)k * 512 + sg * 16);
        }
        CPA_COMMIT();
    }

    float2 bp = *(const float2*)(rule_b + (size_t)r * D_ + cb);
    int out0 = NINIT + lvl * MM;
    unsigned pedst = (unsigned)__cvta_generic_to_shared(pe);

    for (int w0 = 0; w0 < c; w0 += WIN) {
        int wlen = min(WIN, c - w0);
        // stage this window's node + parent indices (one latency hit)
        if (tid < 2 * wlen) {
            int n = tid >> 1, pw = tid & 1;
            int m = g_order[lvl * MM + off0 + w0 + n];
            int p = parents[((size_t)lvl * MM + m) * 2 + pw];
            if (pw == 0) s_m[n] = m;
            s_par[n * 2 + pw] = p;
        }
        __syncthreads();

        int nc = (wlen + CHUNK - 1) / CHUNK;

        // gather one chunk (raw parent rows, 2 x 16B segments per thread)
        auto gather = [&](int buf, int t) {
#pragma unroll
            for (int i = 0; i < 2; i++) {
                int s = i * 256 + tid;           // 0..511
                int n = s >> 6;                  // chunk slot 0..7
                int nn = t * CHUNK + n;          // node in window
                if (nn < wlen) {
                    int rem = s & 63, par = rem >> 5, sx = rem & 31;
                    int p = s_par[nn * 2 + par];
                    cpa16(pedst + (unsigned)(((buf * CHUNK + n) * TWO_D + par * D_) * 4 + sx * 16),
                          (const char*)(g_store + (size_t)p * D_) + sx * 16);
                }
            }
            CPA_COMMIT();
        };

        gather(0, 0);   // prologue

        for (int t = 0; t < nc; t++) {
            int buf = t & 1;
            if (t + 1 < nc) { gather(buf ^ 1, t + 1); CPA_WAIT(1); }
            else            { CPA_WAIT(0); }
            __syncthreads();   // chunk t data (and weights) visible

            int nch = min(CHUNK, wlen - t * CHUNK);
            const float* pev = pe + (size_t)(buf * CHUNK + g) * TWO_D;

            float accx = bp.x, accy = bp.y;
#pragma unroll 8
            for (int k4 = 0; k4 < TWO_D; k4 += 4) {
                float4 v4 = *(const float4*)(pev + k4);
                float2 wa = w_s[(k4 + 0) * 32 + j];
                float2 wb = w_s[(k4 + 1) * 32 + j];
                float2 wc = w_s[(k4 + 2) * 32 + j];
                float2 wd = w_s[(k4 + 3) * 32 + j];
                accx = fmaf(wa.x, v4.x, accx); accy = fmaf(wa.y, v4.x, accy);
                accx = fmaf(wb.x, v4.y, accx); accy = fmaf(wb.y, v4.y, accy);
                accx = fmaf(wc.x, v4.z, accx); accy = fmaf(wc.y, v4.z, accy);
                accx = fmaf(wd.x, v4.w, accx); accy = fmaf(wd.y, v4.w, accy);
            }
            if (g < nch) {
                int m = s_m[t * CHUNK + g];
                float2 o = make_float2(fmaxf(accx, 0.0f), fmaxf(accy, 0.0f));
                *(float2*)(g_store + (size_t)(out0 + m) * D_ + cb) = o;
            }
            __syncthreads();   // protect buf before next gather overwrites it
        }
    }
}

// ---------------- 4. eval: logits + weighted BCE, deterministic reduce ----------------
__global__ void k_eval(const float* __restrict__ eval_w,
                       const float* __restrict__ eval_b,
                       const float* __restrict__ pos_vals,
                       const float* __restrict__ neg_vals) {
    int warp = threadIdx.x >> 5, lane = threadIdx.x & 31;
    int nwarps = gridDim.x * (blockDim.x >> 5);
    int gw = blockIdx.x * (blockDim.x >> 5) + warp;

    const float4 wv = *(const float4*)(eval_w + lane * 4);
    float eb = eval_b[0];

    double s1 = 0, s2 = 0, pok = 0, nok = 0, sp = 0, sn = 0;

    for (int node = gw; node < NTOT; node += nwarps) {
        float4 x = *(const float4*)(g_store + (size_t)node * D_ + lane * 4);
        float d = x.x * wv.x + x.y * wv.y + x.z * wv.z + x.w * wv.w;
#pragma unroll
        for (int o = 16; o > 0; o >>= 1) d += __shfl_xor_sync(0xFFFFFFFFu, d, o);
        if (lane == 0) {
            float logit = d + eb;
            float p = pos_vals[node], n = neg_vals[node];
            s1 += (double)(p * softplusf(-logit));
            s2 += (double)(n * softplusf(logit));
            if (logit >= 0.0f) pok += (double)p; else nok += (double)n;
            sp += (double)p; sn += (double)n;
        }
    }

    __shared__ double sd[8][6];
    if (lane == 0) {
        sd[warp][0] = s1; sd[warp][1] = s2; sd[warp][2] = pok;
        sd[warp][3] = nok; sd[warp][4] = sp; sd[warp][5] = sn;
    }
    __syncthreads();
    if (threadIdx.x == 0) {
        double v[6] = {0, 0, 0, 0, 0, 0};
        for (int w = 0; w < 8; w++)
            for (int c2 = 0; c2 < 6; c2++) v[c2] += sd[w][c2];
        for (int c2 = 0; c2 < 6; c2++) g_part[blockIdx.x * 8 + c2] = v[c2];
    }
}

__global__ void k_final(float* __restrict__ out) {
    __shared__ double sh[6][256];
    int tid = threadIdx.x;
    double v[6] = {0, 0, 0, 0, 0, 0};
    for (int b = tid; b < EVAL_BLOCKS; b += 256)
        for (int c2 = 0; c2 < 6; c2++) v[c2] += g_part[b * 8 + c2];
    for (int c2 = 0; c2 < 6; c2++) sh[c2][tid] = v[c2];
    __syncthreads();
    for (int s = 128; s > 0; s >>= 1) {
        if (tid < s)
            for (int c2 = 0; c2 < 6; c2++) sh[c2][tid] += sh[c2][tid + s];
        __syncthreads();
    }
    if (tid == 0) {
        double S1 = sh[0][0], S2 = sh[1][0], pok = sh[2][0];
        double nok = sh[3][0], sp = sh[4][0], sn = sh[5][0];
        double pw = sn / sp;
        out[0] = (float)(pw * S1 + S2);
        out[1] = (float)pok;
        out[2] = (float)nok;
    }
}

// ---------------- launch ----------------
extern "C" void kernel_launch(void* const* d_in, const int* in_sizes, int n_in,
                              void* d_out, int out_size) {
    const float* thax_table = (const float*)d_in[0];
    const float* sine_table = (const float*)d_in[1];
    const float* rule_W     = (const float*)d_in[2];
    const float* rule_b     = (const float*)d_in[3];
    const float* eval_w     = (const float*)d_in[4];
    const float* eval_b     = (const float*)d_in[5];
    const float* pos_vals   = (const float*)d_in[6];
    const float* neg_vals   = (const float*)d_in[7];
    const int*   init_thax  = (const int*)d_in[8];
    const int*   init_sine  = (const int*)d_in[9];
    const int*   parents    = (const int*)d_in[10];
    const int*   rules      = (const int*)d_in[11];

    (void)in_sizes; (void)n_in; (void)out_size;

    // idempotent, deterministic: allow ~81KB dynamic smem for k_level
    cudaFuncSetAttribute(k_level, cudaFuncAttributeMaxDynamicSharedMemorySize,
                         SMEM_BYTES);

    k_init<<<(NINIT * 32 + 255) / 256, 256>>>(thax_table, sine_table, init_thax, init_sine);
    k_group<<<LVLS, 256>>>(rules);
    for (int l = 0; l < LVLS; l++)
        k_level<<<2 * NRULES, 256, SMEM_BYTES>>>(rule_W, rule_b, parents, l);
    k_eval<<<EVAL_BLOCKS, 256>>>(eval_w, eval_b, pos_vals, neg_vals);
    k_final<<<1, 256>>>((float*)d_out);
}

// round 12
// speedup vs baseline: 1.0804x; 1.0804x over previous
#include <cuda_runtime.h>

// ---------------- problem constants ----------------
#define D_      128
#define TWO_D   256
#define NINIT   100000
#define LVLS    64
#define MM      4096
#define NRULES  256
#define NTOT    (NINIT + LVLS * MM)   // 362144

#define EVAL_BLOCKS 1024
#define CHUNK 16     // nodes per gather chunk (4 g-slots x NN=4)
#define WIN   64     // node-index window staged per rule

// dynamic smem layout for k_level:
//   w_s   float[256][128]           131072 B  (full rule weight matrix)
//   pe    float[2][CHUNK][TWO_D]     32768 B  (raw gathered parents, dbl buf)
//   s_m   int[WIN]                     256 B
//   s_par int[WIN][2]                  512 B
//   mbar  u64[3]                        24 B  (w, buf0, buf1)
#define WS_BYTES  131072
#define PE_BYTES  (2 * CHUNK * TWO_D * 4)
#define IDX_BYTES (WIN * 4 + WIN * 8)
#define SMEM_BYTES (WS_BYTES + PE_BYTES + IDX_BYTES + 64)

// ---------------- device scratch (static: no allocs allowed) ----------------
__device__ float  g_store[(size_t)NTOT * D_];           // ~185 MB embedding store
__device__ int    g_order[LVLS * MM];                   // node ids grouped by rule, per level
__device__ int    g_off[LVLS * (NRULES + 1)];           // per-level rule offsets
__device__ double g_part[EVAL_BLOCKS * 8];              // eval partial sums

// ---------------- bulk-copy / mbarrier helpers ----------------
__device__ __forceinline__ void mbar_init(unsigned mbar, unsigned count) {
    asm volatile("mbarrier.init.shared.b64 [%0], %1;" :: "r"(mbar), "r"(count) : "memory");
}
__device__ __forceinline__ void mbar_expect_tx(unsigned mbar, unsigned bytes) {
    asm volatile("mbarrier.arrive.expect_tx.shared.b64 _, [%0], %1;"
                 :: "r"(mbar), "r"(bytes) : "memory");
}
__device__ __forceinline__ void bulk_g2s(unsigned dst, const void* src,
                                         unsigned bytes, unsigned mbar) {
    asm volatile("cp.async.bulk.shared::cta.global.mbarrier::complete_tx::bytes "
                 "[%0], [%1], %2, [%3];"
                 :: "r"(dst), "l"(src), "r"(bytes), "r"(mbar) : "memory");
}
__device__ __forceinline__ void mbar_wait(unsigned mbar, unsigned phase) {
    asm volatile(
        "{\n\t"
        ".reg .pred p;\n\t"
        "WL%=:\n\t"
        "mbarrier.try_wait.parity.acquire.cta.shared::cta.b64 p, [%0], %1, 0x989680;\n\t"
        "@!p bra WL%=;\n\t"
        "}"
        :: "r"(mbar), "r"(phase) : "memory");
}

__device__ __forceinline__ float softplusf(float x) {
    return fmaxf(x, 0.0f) + log1pf(expf(-fabsf(x)));
}

// ---------------- 1. init embeddings ----------------
__global__ void k_init(const float* __restrict__ thax_table,
                       const float* __restrict__ sine_table,
                       const int* __restrict__ init_thax,
                       const int* __restrict__ init_sine) {
    int idx = blockIdx.x * blockDim.x + threadIdx.x;   // one float4 each
    if (idx >= NINIT * 32) return;
    int row = idx >> 5, q = idx & 31;
    int t = init_thax[row], s = init_sine[row];
    const float4 a = *(const float4*)(thax_table + (size_t)t * D_ + q * 4);
    const float4 b = *(const float4*)(sine_table + (size_t)s * D_ + q * 4);
    float4 o; o.x = a.x + b.x; o.y = a.y + b.y; o.z = a.z + b.z; o.w = a.w + b.w;
    *(float4*)(g_store + (size_t)row * D_ + q * 4) = o;
}

// ---------------- 2. bucket nodes by rule, per level ----------------
__global__ void k_group(const int* __restrict__ rules) {
    int l = blockIdx.x;
    int tid = threadIdx.x;                    // 256 threads
    __shared__ int cnt[NRULES];
    __shared__ int base[NRULES];
    cnt[tid] = 0;
    __syncthreads();
    for (int m = tid; m < MM; m += 256)
        atomicAdd(&cnt[rules[l * MM + m]], 1);
    __syncthreads();
    if (tid == 0) {
        int acc = 0;
        for (int r = 0; r < NRULES; r++) { base[r] = acc; acc += cnt[r]; }
    }
    __syncthreads();
    g_off[l * (NRULES + 1) + tid] = base[tid];
    if (tid == 0) g_off[l * (NRULES + 1) + NRULES] = MM;
    cnt[tid] = 0;
    __syncthreads();
    for (int m = tid; m < MM; m += 256) {
        int r = rules[l * MM + m];
        int pos = base[r] + atomicAdd(&cnt[r], 1);
        g_order[l * MM + pos] = m;            // order within a rule irrelevant
    }
}

// ---------------- 3. level kernel: per-rule MLP, bulk-DMA data movement ------
// One block per rule, 256 threads = 64 col-pairs (j) x 4 node-slots (gs),
// NN=4 nodes per thread -> CHUNK=16 nodes per gather chunk.
// ALL global->shared movement uses cp.async.bulk (1 instr per 128KB weight
// matrix, 1 instr per 512B parent row) with mbarrier completion, eliminating
// the per-instruction LSU floor that capped every prior variant.
__global__ void __launch_bounds__(256) k_level(
    const float* __restrict__ rule_W, const float* __restrict__ rule_b,
    const int* __restrict__ parents, int lvl) {

    int r = blockIdx.x;
    int off0 = g_off[lvl * (NRULES + 1) + r];
    int off1 = g_off[lvl * (NRULES + 1) + r + 1];
    int c = off1 - off0;
    if (c == 0) return;

    extern __shared__ __align__(16) char smem_raw[];
    float* w_s  = (float*)smem_raw;                               // [256][128]
    float* pe   = (float*)(smem_raw + WS_BYTES);                  // [2][CHUNK][256]
    int*   s_m  = (int*)(smem_raw + WS_BYTES + PE_BYTES);         // [WIN]
    int*   s_par= s_m + WIN;                                      // [WIN][2]
    unsigned long long* mb = (unsigned long long*)(s_par + 2 * WIN); // [3]

    unsigned mb_w  = (unsigned)__cvta_generic_to_shared(&mb[0]);
    unsigned mb_b0 = (unsigned)__cvta_generic_to_shared(&mb[1]);
    unsigned mb_b1 = (unsigned)__cvta_generic_to_shared(&mb[2]);
    unsigned pe_sh = (unsigned)__cvta_generic_to_shared(pe);

    int tid = threadIdx.x;
    int j   = tid & 63;            // col-pair 0..63  (cols 2j, 2j+1)
    int gs  = tid >> 6;            // node slot 0..3

    if (tid == 0) {
        mbar_init(mb_w, 1);
        mbar_init(mb_b0, 1);
        mbar_init(mb_b1, 1);
    }
    __syncthreads();

    // ---- weights: ONE 128KB bulk copy ----
    if (tid == 0) {
        mbar_expect_tx(mb_w, WS_BYTES);
        bulk_g2s((unsigned)__cvta_generic_to_shared(w_s),
                 rule_W + (size_t)r * TWO_D * D_, WS_BYTES, mb_w);
    }

    float2 bp = *(const float2*)(rule_b + (size_t)r * D_ + 2 * j);
    int out0 = NINIT + lvl * MM;

    unsigned ph[2] = {0u, 0u};
    bool wready = false;

    for (int w0 = 0; w0 < c; w0 += WIN) {
        int wlen = min(WIN, c - w0);

        // stage this window's node + parent indices
        if (tid < 2 * wlen) {
            int n = tid >> 1, pw = tid & 1;
            int m = g_order[lvl * MM + off0 + w0 + n];
            int p = parents[((size_t)lvl * MM + m) * 2 + pw];
            if (pw == 0) s_m[n] = m;
            s_par[n * 2 + pw] = p;
        }
        __syncthreads();

        int nc = (wlen + CHUNK - 1) / CHUNK;

        // issue gathers for one chunk: 2*nch bulk copies of 512B, tid0 only
        auto gather = [&](int buf, int t) {
            int nch = min(CHUNK, wlen - t * CHUNK);
            unsigned mbar = buf ? mb_b1 : mb_b0;
            mbar_expect_tx(mbar, (unsigned)(nch * 2 * 512));
            for (int i = 0; i < 2 * nch; i++) {
                int n = i >> 1, par = i & 1;
                int p = s_par[(t * CHUNK + n) * 2 + par];
                bulk_g2s(pe_sh + (unsigned)(((buf * CHUNK + n) * TWO_D + par * D_) * 4),
                         g_store + (size_t)p * D_, 512, mbar);
            }
        };

        if (tid == 0) gather(0, 0);   // prologue

        for (int t = 0; t < nc; t++) {
            int buf = t & 1;
            if (t + 1 < nc && tid == 0) gather(buf ^ 1, t + 1);

            mbar_wait(buf ? mb_b1 : mb_b0, ph[buf]);
            ph[buf] ^= 1u;
            if (!wready) { mbar_wait(mb_w, 0u); wready = true; }

            int nch = min(CHUNK, wlen - t * CHUNK);
            const float* pev = pe + (size_t)(buf * CHUNK + gs * 4) * TWO_D;

            float ax0 = bp.x, ay0 = bp.y, ax1 = bp.x, ay1 = bp.y;
            float ax2 = bp.x, ay2 = bp.y, ax3 = bp.x, ay3 = bp.y;

#pragma unroll 4
            for (int k = 0; k < TWO_D; k++) {
                float2 w = *(const float2*)(w_s + k * D_ + 2 * j);
                float v0 = pev[0 * TWO_D + k];
                float v1 = pev[1 * TWO_D + k];
                float v2 = pev[2 * TWO_D + k];
                float v3 = pev[3 * TWO_D + k];
                ax0 = fmaf(w.x, v0, ax0); ay0 = fmaf(w.y, v0, ay0);
                ax1 = fmaf(w.x, v1, ax1); ay1 = fmaf(w.y, v1, ay1);
                ax2 = fmaf(w.x, v2, ax2); ay2 = fmaf(w.y, v2, ay2);
                ax3 = fmaf(w.x, v3, ax3); ay3 = fmaf(w.y, v3, ay3);
            }

            float2 o;
            int nb = t * CHUNK + gs * 4;
            if (nb + 0 < wlen) {
                o = make_float2(fmaxf(ax0, 0.f), fmaxf(ay0, 0.f));
                *(float2*)(g_store + (size_t)(out0 + s_m[nb + 0]) * D_ + 2 * j) = o;
            }
            if (nb + 1 < wlen) {
                o = make_float2(fmaxf(ax1, 0.f), fmaxf(ay1, 0.f));
                *(float2*)(g_store + (size_t)(out0 + s_m[nb + 1]) * D_ + 2 * j) = o;
            }
            if (nb + 2 < wlen) {
                o = make_float2(fmaxf(ax2, 0.f), fmaxf(ay2, 0.f));
                *(float2*)(g_store + (size_t)(out0 + s_m[nb + 2]) * D_ + 2 * j) = o;
            }
            if (nb + 3 < wlen) {
                o = make_float2(fmaxf(ax3, 0.f), fmaxf(ay3, 0.f));
                *(float2*)(g_store + (size_t)(out0 + s_m[nb + 3]) * D_ + 2 * j) = o;
            }
            (void)nch;
            __syncthreads();   // buf consumed before it is re-gathered / idx restaged
        }
    }
}

// ---------------- 4. eval: logits + weighted BCE, deterministic reduce ----------------
__global__ void k_eval(const float* __restrict__ eval_w,
                       const float* __restrict__ eval_b,
                       const float* __restrict__ pos_vals,
                       const float* __restrict__ neg_vals) {
    int warp = threadIdx.x >> 5, lane = threadIdx.x & 31;
    int nwarps = gridDim.x * (blockDim.x >> 5);
    int gw = blockIdx.x * (blockDim.x >> 5) + warp;

    const float4 wv = *(const float4*)(eval_w + lane * 4);
    float eb = eval_b[0];

    double s1 = 0, s2 = 0, pok = 0, nok = 0, sp = 0, sn = 0;

    for (int node = gw; node < NTOT; node += nwarps) {
        float4 x = *(const float4*)(g_store + (size_t)node * D_ + lane * 4);
        float d = x.x * wv.x + x.y * wv.y + x.z * wv.z + x.w * wv.w;
#pragma unroll
        for (int o = 16; o > 0; o >>= 1) d += __shfl_xor_sync(0xFFFFFFFFu, d, o);
        if (lane == 0) {
            float logit = d + eb;
            float p = pos_vals[node], n = neg_vals[node];
            s1 += (double)(p * softplusf(-logit));
            s2 += (double)(n * softplusf(logit));
            if (logit >= 0.0f) pok += (double)p; else nok += (double)n;
            sp += (double)p; sn += (double)n;
        }
    }

    __shared__ double sd[8][6];
    if (lane == 0) {
        sd[warp][0] = s1; sd[warp][1] = s2; sd[warp][2] = pok;
        sd[warp][3] = nok; sd[warp][4] = sp; sd[warp][5] = sn;
    }
    __syncthreads();
    if (threadIdx.x == 0) {
        double v[6] = {0, 0, 0, 0, 0, 0};
        for (int w = 0; w < 8; w++)
            for (int c2 = 0; c2 < 6; c2++) v[c2] += sd[w][c2];
        for (int c2 = 0; c2 < 6; c2++) g_part[blockIdx.x * 8 + c2] = v[c2];
    }
}

__global__ void k_final(float* __restrict__ out) {
    __shared__ double sh[6][256];
    int tid = threadIdx.x;
    double v[6] = {0, 0, 0, 0, 0, 0};
    for (int b = tid; b < EVAL_BLOCKS; b += 256)
        for (int c2 = 0; c2 < 6; c2++) v[c2] += g_part[b * 8 + c2];
    for (int c2 = 0; c2 < 6; c2++) sh[c2][tid] = v[c2];
    __syncthreads();
    for (int s = 128; s > 0; s >>= 1) {
        if (tid < s)
            for (int c2 = 0; c2 < 6; c2++) sh[c2][tid] += sh[c2][tid + s];
        __syncthreads();
    }
    if (tid == 0) {
        double S1 = sh[0][0], S2 = sh[1][0], pok = sh[2][0];
        double nok = sh[3][0], sp = sh[4][0], sn = sh[5][0];
        double pw = sn / sp;
        out[0] = (float)(pw * S1 + S2);
        out[1] = (float)pok;
        out[2] = (float)nok;
    }
}

// ---------------- launch ----------------
extern "C" void kernel_launch(void* const* d_in, const int* in_sizes, int n_in,
                              void* d_out, int out_size) {
    const float* thax_table = (const float*)d_in[0];
    const float* sine_table = (const float*)d_in[1];
    const float* rule_W     = (const float*)d_in[2];
    const float* rule_b     = (const float*)d_in[3];
    const float* eval_w     = (const float*)d_in[4];
    const float* eval_b     = (const float*)d_in[5];
    const float* pos_vals   = (const float*)d_in[6];
    const float* neg_vals   = (const float*)d_in[7];
    const int*   init_thax  = (const int*)d_in[8];
    const int*   init_sine  = (const int*)d_in[9];
    const int*   parents    = (const int*)d_in[10];
    const int*   rules      = (const int*)d_in[11];

    (void)in_sizes; (void)n_in; (void)out_size;

    // idempotent, deterministic: allow ~161KB dynamic smem for k_level
    cudaFuncSetAttribute(k_level, cudaFuncAttributeMaxDynamicSharedMemorySize,
                         SMEM_BYTES);

    k_init<<<(NINIT * 32 + 255) / 256, 256>>>(thax_table, sine_table, init_thax, init_sine);
    k_group<<<LVLS, 256>>>(rules);
    for (int l = 0; l < LVLS; l++)
        k_level<<<NRULES, 256, SMEM_BYTES>>>(rule_W, rule_b, parents, l);
    k_eval<<<EVAL_BLOCKS, 256>>>(eval_w, eval_b, pos_vals, neg_vals);
    k_final<<<1, 256>>>((float*)d_out);
}